// round 13
// baseline (speedup 1.0000x reference)
#include <cuda_runtime.h>

#define NF      26
#define VOCAB   100000
#define EMBED   16
#define BATCH   16384
#define KDIM    16
#define NTOT    (NF * EMBED)   // 416
#define VSTRIDE 20             // [v0..v15, W, s2, pad, pad] -> conflict-free float4 LDS
#define ESTRIDE 424            // e-row stride: 424 mod 16 == 8 -> halves complementary banks
#define ROWS    16             // rows per block
#define THREADS 128

extern __shared__ float smem[];

__global__ __launch_bounds__(THREADS)
void fm_kernel(const int* __restrict__ X,
               const float* __restrict__ tables,
               const float* __restrict__ W,
               const float* __restrict__ bptr,
               const float* __restrict__ v,
               float* __restrict__ out)
{
    float* v_sh = smem;                        // [NTOT][VSTRIDE]   33280 B
    float* e_sh = smem + NTOT * VSTRIDE;       // [ROWS][ESTRIDE]   27136 B

    const int tid = threadIdx.x;

    // ---- Phase 0: stage augmented v tile: row n = [v[n][0..15], W[n], s2[n], 0, 0]
    for (int n = tid; n < NTOT; n += THREADS) {
        const float4* vr = (const float4*)(v + n * KDIM);
        float s2 = 0.f;
#pragma unroll
        for (int q = 0; q < 4; q++) {
            float4 a = vr[q];
            ((float4*)(v_sh + n * VSTRIDE))[q] = a;
            s2 += a.x * a.x + a.y * a.y + a.z * a.z + a.w * a.w;
        }
        v_sh[n * VSTRIDE + 16] = __ldg(&W[n]);
        v_sh[n * VSTRIDE + 17] = s2;
        v_sh[n * VSTRIDE + 18] = 0.f;
        v_sh[n * VSTRIDE + 19] = 0.f;
    }

    // ---- Phase 1: cooperative gather of all embeddings for this block's rows.
    // 16 rows x 26 fields x 4 float4 = 1664 items = 13 per thread, all independent.
    const int base_row = blockIdx.x * ROWS;
#pragma unroll
    for (int w = 0; w < 13; w++) {
        int item = w * THREADS + tid;
        int r    = item / (NF * 4);
        int rest = item - r * (NF * 4);
        int f    = rest >> 2;
        int q    = rest & 3;
        int idx  = __ldg(&X[(base_row + r) * NF + f]);
        float4 ev = __ldg((const float4*)(tables
                        + ((long long)f * VOCAB + idx) * EMBED) + q);
        *((float4*)(e_sh + r * ESTRIDE + f * EMBED) + q) = ev;
    }

    const int lane = tid & 31;
    const int j    = lane & 15;                // embedding component owned by this lane
    const int warp = tid >> 5;
    // Warp covers 4 rows: lanes 0-15 -> rows l0,l0+1 ; lanes 16-31 -> l0+2,l0+3.
    const int l0   = warp * 4 + (lane >> 4) * 2;
    const int row0 = base_row + l0;
    const float bval = __ldg(bptr);

    __syncthreads();

    float a0[KDIM], a1[KDIM];
#pragma unroll
    for (int k = 0; k < KDIM; k++) { a0[k] = 0.f; a1[k] = 0.f; }
    float lin0 = 0.f, lin1 = 0.f;              // partial sum_n e_n * W_n (this lane's j)
    float ss0  = 0.f, ss1  = 0.f;              // partial sum_n e_n^2 * s2_n

    const float* e0base = e_sh + l0 * ESTRIDE + j;
    const float* e1base = e0base + ESTRIDE;

#pragma unroll
    for (int f = 0; f < NF; f++) {
        float e0 = e0base[f * EMBED];          // LDS.32, halves on complementary banks
        float e1 = e1base[f * EMBED];

        const float* rbase = v_sh + (f * EMBED + j) * VSTRIDE;
#pragma unroll
        for (int kq = 0; kq < 4; kq++) {
            float4 a = ((const float4*)rbase)[kq];
            a0[kq * 4 + 0] = fmaf(e0, a.x, a0[kq * 4 + 0]);
            a0[kq * 4 + 1] = fmaf(e0, a.y, a0[kq * 4 + 1]);
            a0[kq * 4 + 2] = fmaf(e0, a.z, a0[kq * 4 + 2]);
            a0[kq * 4 + 3] = fmaf(e0, a.w, a0[kq * 4 + 3]);
            a1[kq * 4 + 0] = fmaf(e1, a.x, a1[kq * 4 + 0]);
            a1[kq * 4 + 1] = fmaf(e1, a.y, a1[kq * 4 + 1]);
            a1[kq * 4 + 2] = fmaf(e1, a.z, a1[kq * 4 + 2]);
            a1[kq * 4 + 3] = fmaf(e1, a.w, a1[kq * 4 + 3]);
        }
        float4 ws = ((const float4*)rbase)[4]; // .x = W[n], .y = s2[n]
        lin0 = fmaf(e0,      ws.x, lin0);
        lin1 = fmaf(e1,      ws.x, lin1);
        ss0  = fmaf(e0 * e0, ws.y, ss0);
        ss1  = fmaf(e1 * e1, ws.y, ss1);
    }

    // Transpose-reduce across the 16-lane half: after 4 levels a0[0] holds a FULL
    // j-sum of one xv component (k-permutation is harmless: final use is sum of
    // squares). 15 shfl per row instead of 64. XOR offsets <= 8 stay in-half.
#pragma unroll
    for (int off = 8; off >= 1; off >>= 1) {
#pragma unroll
        for (int i = 0; i < off; i++) {
            const int keep = (j & off) ? i + off : i;
            const int send = (j & off) ? i : i + off;
            float u0 = __shfl_xor_sync(0xffffffffu, a0[send], off);
            float u1 = __shfl_xor_sync(0xffffffffu, a1[send], off);
            a0[i] = a0[keep] + u0;
            a1[i] = a1[keep] + u1;
        }
    }

    // Per-lane scalar: 0.5*xv_k^2 (its k) + lin_partial - 0.5*ss_partial,
    // then one scalar butterfly over the half-warp.
    float c0 = fmaf(0.5f * a0[0], a0[0], fmaf(-0.5f, ss0, lin0));
    float c1 = fmaf(0.5f * a1[0], a1[0], fmaf(-0.5f, ss1, lin1));
#pragma unroll
    for (int off = 8; off >= 1; off >>= 1) {
        c0 += __shfl_xor_sync(0xffffffffu, c0, off);
        c1 += __shfl_xor_sync(0xffffffffu, c1, off);
    }

    if (j == 0) {
        float z0 = c0 + bval;
        float z1 = c1 + bval;
        out[row0]     = 1.f / (1.f + __expf(-z0));
        out[row0 + 1] = 1.f / (1.f + __expf(-z1));
    }
}

extern "C" void kernel_launch(void* const* d_in, const int* in_sizes, int n_in,
                              void* d_out, int out_size)
{
    const int*   X      = (const int*)d_in[0];
    const float* tables = (const float*)d_in[1];
    const float* W      = (const float*)d_in[2];
    const float* b      = (const float*)d_in[3];
    const float* v      = (const float*)d_in[4];
    float*       out    = (float*)d_out;

    const size_t shmem = (size_t)(NTOT * VSTRIDE + ROWS * ESTRIDE) * sizeof(float); // 60416 B
    cudaFuncSetAttribute(fm_kernel, cudaFuncAttributeMaxDynamicSharedMemorySize,
                         (int)shmem);

    // 16 rows per block (4 warps x 4 rows), 1024 blocks covers BATCH=16384.
    fm_kernel<<<BATCH / ROWS, THREADS, shmem>>>(X, tables, W, b, v, out);
}